// round 3
// baseline (speedup 1.0000x reference)
#include <cuda_runtime.h>
#include <cstddef>

#define N_NODES 50000
#define N_EDGES 200000
#define NB      64
#define DIN_N   64
#define DIN_E   16
#define DN      128
#define DE      64
#define DHID    64
#define NL      6

#define TE 56          // edges per tile (edge kernel), 448 threads
#define TN 32          // nodes per tile (node kernel), 256 threads
#define HS_STRIDE 132
#define E_STRIDE  68

typedef unsigned long long u64;

// ---------------- scratch ----------------
__device__ float g_h[(size_t)N_NODES * DN];
__device__ float g_e[(size_t)N_EDGES * DE];
__device__ float g_m[(size_t)N_NODES * DE];
__device__ float g_deg[N_NODES];
__device__ float g_gsum[NB * DN];
__device__ float g_gcnt[NB];
__device__ float g_rtmp[NB * DN];

// ---------------- packed f32x2 helpers ----------------
__device__ __forceinline__ void fma2(u64& d, u64 a, u64 b) {
    asm("fma.rn.f32x2 %0, %1, %2, %0;" : "+l"(d) : "l"(a), "l"(b));
}
__device__ __forceinline__ u64 pack2(float x) {
    u64 r; asm("mov.b64 %0, {%1, %1};" : "=l"(r) : "f"(x)); return r;
}
__device__ __forceinline__ float2 unpack2(u64 v) {
    float2 f; asm("mov.b64 {%0, %1}, %2;" : "=f"(f.x), "=f"(f.y) : "l"(v)); return f;
}

// acc[0..3] += arow[0..kdim) * w[k*ldw + j0 .. +8)   (8 output cols as 4 f32x2)
__device__ __forceinline__ void gemm8(const float* __restrict__ arow,
                                      const float* __restrict__ w,
                                      int ldw, int kdim, int j0, u64* acc) {
#pragma unroll 4
    for (int k = 0; k < kdim; k += 4) {
        float4 av = *(const float4*)(arow + k);
#pragma unroll
        for (int kk = 0; kk < 4; kk++) {
            float a = (&av.x)[kk];
            u64 a2 = pack2(a);
            const float* wp = w + (k + kk) * ldw + j0;
            ulonglong2 p = *(const ulonglong2*)(wp);
            ulonglong2 q = *(const ulonglong2*)(wp + 4);
            fma2(acc[0], a2, p.x); fma2(acc[1], a2, p.y);
            fma2(acc[2], a2, q.x); fma2(acc[3], a2, q.y);
        }
    }
}

// acc[0..7] += arow * w  (16 output cols)
__device__ __forceinline__ void gemm16(const float* __restrict__ arow,
                                       const float* __restrict__ w,
                                       int ldw, int kdim, int j0, u64* acc) {
#pragma unroll 4
    for (int k = 0; k < kdim; k += 4) {
        float4 av = *(const float4*)(arow + k);
#pragma unroll
        for (int kk = 0; kk < 4; kk++) {
            float a = (&av.x)[kk];
            u64 a2 = pack2(a);
            const float* wp = w + (k + kk) * ldw + j0;
            ulonglong2 p = *(const ulonglong2*)(wp);
            ulonglong2 q = *(const ulonglong2*)(wp + 4);
            ulonglong2 s = *(const ulonglong2*)(wp + 8);
            ulonglong2 t = *(const ulonglong2*)(wp + 12);
            fma2(acc[0], a2, p.x); fma2(acc[1], a2, p.y);
            fma2(acc[2], a2, q.x); fma2(acc[3], a2, q.y);
            fma2(acc[4], a2, s.x); fma2(acc[5], a2, s.y);
            fma2(acc[6], a2, t.x); fma2(acc[7], a2, t.y);
        }
    }
}

// ---------------- helpers ----------------
__global__ void zero_kernel(float* p, int n) {
    int i = blockIdx.x * blockDim.x + threadIdx.x;
    if (i < n) p[i] = 0.f;
}

__global__ void deg_kernel(const int* __restrict__ dst) {
    int i = blockIdx.x * blockDim.x + threadIdx.x;
    if (i < N_EDGES) atomicAdd(&g_deg[dst[i]], 1.f);
}

__global__ void node_enc_kernel(const float* __restrict__ x,
                                const float* __restrict__ w,
                                const float* __restrict__ b) {
    __shared__ float xs[DIN_N];
    int nidx = blockIdx.x;
    int j = threadIdx.x;
    if (j < DIN_N) xs[j] = x[(size_t)nidx * DIN_N + j];
    __syncthreads();
    float acc = b[j];
#pragma unroll 8
    for (int k = 0; k < DIN_N; k++) acc = fmaf(xs[k], w[k * DN + j], acc);
    g_h[(size_t)nidx * DN + j] = acc;
}

__global__ void edge_enc_kernel(const float* __restrict__ ea,
                                const float* __restrict__ w,
                                const float* __restrict__ b) {
    __shared__ float es[4][DIN_E];
    int base = blockIdx.x * 4;
    int tid = threadIdx.x;
    if (tid < 64) es[tid >> 4][tid & 15] = ea[(size_t)base * DIN_E + tid];
    __syncthreads();
    int i = tid >> 6;
    int j = tid & 63;
    float acc = b[j];
#pragma unroll
    for (int k = 0; k < DIN_E; k++) acc = fmaf(es[i][k], w[k * DE + j], acc);
    g_e[(size_t)(base + i) * DE + j] = acc;
}

// ---------------- per-layer edge update ----------------
__global__ void __launch_bounds__(448, 1)
edge_layer_kernel(const int* __restrict__ src, const int* __restrict__ dst,
                  const float* __restrict__ mw, const float* __restrict__ w1,
                  const float* __restrict__ b1, const float* __restrict__ w2,
                  const float* __restrict__ b2) {
    extern __shared__ float sm[];
    float* mw_s = sm;                               // 128*64
    float* w1_s = mw_s + DN * DE;                   // 320*64
    float* w2_s = w1_s + (DE + 2 * DN) * DHID;      // 64*64
    float* b1_s = w2_s + DHID * DE;                 // 64
    float* b2_s = b1_s + DHID;                      // 64
    float* hs_s = b2_s + DE;                        // TE*132
    float* hd_s = hs_s + TE * HS_STRIDE;            // TE*132
    float* e_s  = hd_s + TE * HS_STRIDE;            // TE*68
    float* t_s  = e_s  + TE * E_STRIDE;             // TE*68 (u overlays t)

    const int tid = threadIdx.x;
    for (int idx = tid; idx < DN * DE; idx += 448) mw_s[idx] = mw[idx];
    for (int idx = tid; idx < (DE + 2 * DN) * DHID; idx += 448) w1_s[idx] = w1[idx];
    for (int idx = tid; idx < DHID * DE; idx += 448) w2_s[idx] = w2[idx];
    if (tid < DHID) b1_s[tid] = b1[tid];
    else if (tid >= 64 && tid < 64 + DE) b2_s[tid - 64] = b2[tid - 64];
    __syncthreads();

    const int i  = tid >> 3;     // edge-in-tile 0..55
    const int r  = tid & 7;
    const int j0 = r << 3;

    for (int tile = blockIdx.x * TE; tile < N_EDGES; tile += gridDim.x * TE) {
        const int e0 = tile + i;
        const bool ok = e0 < N_EDGES;
        const int eidx = ok ? e0 : 0;
        const int s = src[eidx];
        const int d = dst[eidx];
        {
            const float4* hsp = (const float4*)(g_h + (size_t)s * DN);
            const float4* hdp = (const float4*)(g_h + (size_t)d * DN);
#pragma unroll
            for (int q = 0; q < 4; q++) {
                int c = (r + 8 * q) << 2;
                *(float4*)(hs_s + i * HS_STRIDE + c) = hsp[r + 8 * q];
                *(float4*)(hd_s + i * HS_STRIDE + c) = hdp[r + 8 * q];
            }
            const float4* ep = (const float4*)(g_e + (size_t)eidx * DE);
#pragma unroll
            for (int q = 0; q < 2; q++) {
                int c = (r * 2 + q) << 2;
                *(float4*)(e_s + i * E_STRIDE + c) = ep[r * 2 + q];
            }
        }
        __syncthreads();

        // -------- t = e + hs @ mw --------
        u64 acc[4] = {0ull, 0ull, 0ull, 0ull};
        gemm8(hs_s + i * HS_STRIDE, mw_s, DE, DN, j0, acc);
#pragma unroll
        for (int c = 0; c < 4; c++) {
            float2 f = unpack2(acc[c]);
            t_s[i * E_STRIDE + j0 + 2 * c]     = e_s[i * E_STRIDE + j0 + 2 * c] + f.x;
            t_s[i * E_STRIDE + j0 + 2 * c + 1] = e_s[i * E_STRIDE + j0 + 2 * c + 1] + f.y;
        }
        __syncthreads();

        // -------- u = relu([hs,hd,t] @ w1 + b1)  (u overlays t) --------
        acc[0] = acc[1] = acc[2] = acc[3] = 0ull;
        gemm8(hs_s + i * HS_STRIDE, w1_s, DHID, DN, j0, acc);
        gemm8(hd_s + i * HS_STRIDE, w1_s + DN * DHID, DHID, DN, j0, acc);
        gemm8(t_s + i * E_STRIDE, w1_s + 2 * DN * DHID, DHID, DE, j0, acc);
        __syncwarp();   // all lanes of this warp done reading t-rows before overlay write
#pragma unroll
        for (int c = 0; c < 4; c++) {
            float2 f = unpack2(acc[c]);
            t_s[i * E_STRIDE + j0 + 2 * c]     = fmaxf(f.x + b1_s[j0 + 2 * c], 0.f);
            t_s[i * E_STRIDE + j0 + 2 * c + 1] = fmaxf(f.y + b1_s[j0 + 2 * c + 1], 0.f);
        }
        __syncthreads();

        // -------- e_new = e + u @ w2 + b2 ; store + scatter-add --------
        acc[0] = acc[1] = acc[2] = acc[3] = 0ull;
        gemm8(t_s + i * E_STRIDE, w2_s, DE, DHID, j0, acc);
        if (ok) {
            float* eo = g_e + (size_t)eidx * DE + j0;
            float* mo = g_m + (size_t)d * DE + j0;
#pragma unroll
            for (int c = 0; c < 4; c++) {
                float2 f = unpack2(acc[c]);
                float en0 = e_s[i * E_STRIDE + j0 + 2 * c]     + f.x + b2_s[j0 + 2 * c];
                float en1 = e_s[i * E_STRIDE + j0 + 2 * c + 1] + f.y + b2_s[j0 + 2 * c + 1];
                eo[2 * c] = en0; eo[2 * c + 1] = en1;
                atomicAdd(mo + 2 * c, en0);
                atomicAdd(mo + 2 * c + 1, en1);
            }
        }
        __syncthreads();
    }
}

// ---------------- per-layer node update ----------------
__global__ void __launch_bounds__(256, 2)
node_layer_kernel(const float* __restrict__ w1, const float* __restrict__ b1,
                  const float* __restrict__ w2, const float* __restrict__ b2) {
    extern __shared__ float sm[];
    float* w1_s = sm;                             // 192*64
    float* w2_s = w1_s + (DN + DE) * DHID;        // 64*128
    float* b1_s = w2_s + DHID * DN;               // 64
    float* b2_s = b1_s + DHID;                    // 128
    float* h_s  = b2_s + DN;                      // TN*132
    float* m_s  = h_s + TN * HS_STRIDE;           // TN*68 (u overlays m)

    const int tid = threadIdx.x;
    for (int idx = tid; idx < (DN + DE) * DHID; idx += 256) w1_s[idx] = w1[idx];
    for (int idx = tid; idx < DHID * DN; idx += 256) w2_s[idx] = w2[idx];
    if (tid < DHID) b1_s[tid] = b1[tid];
    if (tid < DN)   b2_s[tid] = b2[tid];
    __syncthreads();

    const int i  = tid >> 3;
    const int r  = tid & 7;
    const int j0 = r << 3;

    for (int tile = blockIdx.x * TN; tile < N_NODES; tile += gridDim.x * TN) {
        const int n0 = tile + i;
        const bool ok = n0 < N_NODES;
        const int node = ok ? n0 : 0;
        {
            const float4* hp = (const float4*)(g_h + (size_t)node * DN);
#pragma unroll
            for (int q = 0; q < 4; q++) {
                int c = (r + 8 * q) << 2;
                *(float4*)(h_s + i * HS_STRIDE + c) = hp[r + 8 * q];
            }
            const float inv = 1.f / fmaxf(g_deg[node], 1.f);
            const float4* mp = (const float4*)(g_m + (size_t)node * DE);
#pragma unroll
            for (int q = 0; q < 2; q++) {
                float4 v = mp[r * 2 + q];
                int c = (r * 2 + q) << 2;
                m_s[i * E_STRIDE + c]     = v.x * inv;
                m_s[i * E_STRIDE + c + 1] = v.y * inv;
                m_s[i * E_STRIDE + c + 2] = v.z * inv;
                m_s[i * E_STRIDE + c + 3] = v.w * inv;
            }
        }
        __syncthreads();

        // u = relu([h, m] @ w1 + b1)   (u overlays m)
        u64 acc[4] = {0ull, 0ull, 0ull, 0ull};
        gemm8(h_s + i * HS_STRIDE, w1_s, DHID, DN, j0, acc);
        gemm8(m_s + i * E_STRIDE, w1_s + DN * DHID, DHID, DE, j0, acc);
        __syncwarp();
#pragma unroll
        for (int c = 0; c < 4; c++) {
            float2 f = unpack2(acc[c]);
            m_s[i * E_STRIDE + j0 + 2 * c]     = fmaxf(f.x + b1_s[j0 + 2 * c], 0.f);
            m_s[i * E_STRIDE + j0 + 2 * c + 1] = fmaxf(f.y + b1_s[j0 + 2 * c + 1], 0.f);
        }
        __syncthreads();

        // h = h + u @ w2 + b2   (16 out cols per thread)
        u64 acc2[8];
#pragma unroll
        for (int c = 0; c < 8; c++) acc2[c] = 0ull;
        const int j0b = r << 4;
        gemm16(m_s + i * E_STRIDE, w2_s, DN, DHID, j0b, acc2);
        if (ok) {
            float* ho = g_h + (size_t)node * DN + j0b;
#pragma unroll
            for (int c = 0; c < 8; c++) {
                float2 f = unpack2(acc2[c]);
                ho[2 * c]     = h_s[i * HS_STRIDE + j0b + 2 * c]     + f.x + b2_s[j0b + 2 * c];
                ho[2 * c + 1] = h_s[i * HS_STRIDE + j0b + 2 * c + 1] + f.y + b2_s[j0b + 2 * c + 1];
            }
        }
        __syncthreads();
    }
}

// ---------------- readout (segmented: batch is sorted) ----------------
__global__ void readout_kernel(const int* __restrict__ batch) {
    int c = threadIdx.x;                 // channel 0..127
    int n0 = blockIdx.x * 128;
    if (n0 >= N_NODES) return;
    int n1 = n0 + 128; if (n1 > N_NODES) n1 = N_NODES;
    int cur = batch[n0];
    float s = 0.f, cnt = 0.f;
#pragma unroll 4
    for (int node = n0; node < n1; node++) {
        int bb = batch[node];
        if (bb != cur) {
            atomicAdd(&g_gsum[cur * DN + c], s);
            if (c == 0) atomicAdd(&g_gcnt[cur], cnt);
            s = 0.f; cnt = 0.f; cur = bb;
        }
        s += g_h[(size_t)node * DN + c];
        cnt += 1.f;
    }
    atomicAdd(&g_gsum[cur * DN + c], s);
    if (c == 0) atomicAdd(&g_gcnt[cur], cnt);
}

__global__ void ro1_kernel(const float* __restrict__ w, const float* __restrict__ b) {
    __shared__ float gx[DN];
    int g = blockIdx.x, j = threadIdx.x;
    gx[j] = g_gsum[g * DN + j] / fmaxf(g_gcnt[g], 1.f);
    __syncthreads();
    float acc = b[j];
#pragma unroll 8
    for (int k = 0; k < DN; k++) acc = fmaf(gx[k], w[k * DN + j], acc);
    g_rtmp[g * DN + j] = fmaxf(acc, 0.f);
}

__global__ void ro2_kernel(const float* __restrict__ w, const float* __restrict__ b,
                           float* __restrict__ out) {
    __shared__ float gx[DN];
    int g = blockIdx.x, j = threadIdx.x;
    gx[j] = g_rtmp[g * DN + j];
    __syncthreads();
    float acc = b[j];
#pragma unroll 8
    for (int k = 0; k < DN; k++) acc = fmaf(gx[k], w[k * DN + j], acc);
    out[g * DN + j] = acc;
}

// ---------------- host ----------------
static const int EDGE_SMEM_BYTES =
    (DN * DE + (DE + 2 * DN) * DHID + DHID * DE + DHID + DE +
     2 * TE * HS_STRIDE + 2 * TE * E_STRIDE) * 4;   // 221184
static const int NODE_SMEM_BYTES =
    ((DN + DE) * DHID + DHID * DN + DHID + DN +
     TN * HS_STRIDE + TN * E_STRIDE) * 4;           // 108288

extern "C" void kernel_launch(void* const* d_in, const int* in_sizes, int n_in,
                              void* d_out, int out_size) {
    const float* x       = (const float*)d_in[0];
    const float* ea      = (const float*)d_in[1];
    const int*   eindex  = (const int*)d_in[2];
    const int*   batch   = (const int*)d_in[3];
    const float* lin_x_w = (const float*)d_in[4];
    const float* lin_x_b = (const float*)d_in[5];
    const float* lin_e_w = (const float*)d_in[6];
    const float* lin_e_b = (const float*)d_in[7];
    const float* msg_w   = (const float*)d_in[8];
    const float* pe_w1   = (const float*)d_in[9];
    const float* pe_b1   = (const float*)d_in[10];
    const float* pe_w2   = (const float*)d_in[11];
    const float* pe_b2   = (const float*)d_in[12];
    const float* pv_w1   = (const float*)d_in[13];
    const float* pv_b1   = (const float*)d_in[14];
    const float* pv_w2   = (const float*)d_in[15];
    const float* pv_b2   = (const float*)d_in[16];
    const float* ro_w1   = (const float*)d_in[17];
    const float* ro_b1   = (const float*)d_in[18];
    const float* ro_w2   = (const float*)d_in[19];
    const float* ro_b2   = (const float*)d_in[20];
    const int* src = eindex;
    const int* dst = eindex + N_EDGES;

    cudaFuncSetAttribute(edge_layer_kernel,
                         cudaFuncAttributeMaxDynamicSharedMemorySize, EDGE_SMEM_BYTES);
    cudaFuncSetAttribute(node_layer_kernel,
                         cudaFuncAttributeMaxDynamicSharedMemorySize, NODE_SMEM_BYTES);

    float *p_deg, *p_m, *p_gs, *p_gc;
    cudaGetSymbolAddress((void**)&p_deg, g_deg);
    cudaGetSymbolAddress((void**)&p_m,   g_m);
    cudaGetSymbolAddress((void**)&p_gs,  g_gsum);
    cudaGetSymbolAddress((void**)&p_gc,  g_gcnt);

    // launch order chosen so edge_layer(l=0) is the 4th launch (ncu -s 5 offset
    // observed to land on my index-3 kernel last round)
    node_enc_kernel<<<N_NODES, 128>>>(x, lin_x_w, lin_x_b);          // 0
    edge_enc_kernel<<<N_EDGES / 4, 256>>>(ea, lin_e_w, lin_e_b);     // 1
    zero_kernel<<<(N_NODES * DE + 255) / 256, 256>>>(p_m, N_NODES * DE); // 2
    edge_layer_kernel<<<148, 448, EDGE_SMEM_BYTES>>>(                // 3  <- profile target
        src, dst, msg_w, pe_w1, pe_b1, pe_w2, pe_b2);
    zero_kernel<<<(N_NODES + 255) / 256, 256>>>(p_deg, N_NODES);     // 4
    deg_kernel<<<(N_EDGES + 255) / 256, 256>>>(dst);                 // 5
    node_layer_kernel<<<296, 256, NODE_SMEM_BYTES>>>(                // 6
        pv_w1, pv_b1, pv_w2, pv_b2);

    for (int l = 1; l < NL; l++) {
        zero_kernel<<<(N_NODES * DE + 255) / 256, 256>>>(p_m, N_NODES * DE);
        edge_layer_kernel<<<148, 448, EDGE_SMEM_BYTES>>>(
            src, dst,
            msg_w + (size_t)l * DN * DE,
            pe_w1 + (size_t)l * (DE + 2 * DN) * DHID,
            pe_b1 + (size_t)l * DHID,
            pe_w2 + (size_t)l * DHID * DE,
            pe_b2 + (size_t)l * DE);
        node_layer_kernel<<<296, 256, NODE_SMEM_BYTES>>>(
            pv_w1 + (size_t)l * (DN + DE) * DHID,
            pv_b1 + (size_t)l * DHID,
            pv_w2 + (size_t)l * DHID * DN,
            pv_b2 + (size_t)l * DN);
    }

    zero_kernel<<<(NB * DN + 255) / 256, 256>>>(p_gs, NB * DN);
    zero_kernel<<<1, 64>>>(p_gc, NB);
    readout_kernel<<<(N_NODES + 127) / 128, 128>>>(batch);
    ro1_kernel<<<NB, DN>>>(ro_w1, ro_b1);
    ro2_kernel<<<NB, DN>>>(ro_w2, ro_b2, (float*)d_out);
}

// round 6
// speedup vs baseline: 7.1464x; 7.1464x over previous
#include <cuda_runtime.h>
#include <cstddef>

#define N_NODES 50000
#define N_EDGES 200000
#define NB      64
#define DIN_N   64
#define DIN_E   16
#define DN      128
#define DE      64
#define DHID    64
#define NL      6

#define TEE 128      // edges per tile (edge kernel)
#define TNN 128      // nodes per tile (node kernel)
#define TP  128      // nodes per tile (precompute kernel)

// ---------------- scratch ----------------
__device__ float g_h[(size_t)N_NODES * DN];
__device__ float g_e[(size_t)N_EDGES * DE];
__device__ float g_m[(size_t)N_NODES * DE];
__device__ float g_pre[(size_t)N_NODES * 192];   // [m0 | p1 | p2] per node
__device__ float g_deg[N_NODES];
__device__ float g_gsum[NB * DN];
__device__ float g_gcnt[NB];
__device__ float g_rtmp[NB * DN];

__device__ __forceinline__ void fma8(float* acc, float a, float4 wA, float4 wB) {
    acc[0] = fmaf(a, wA.x, acc[0]); acc[1] = fmaf(a, wA.y, acc[1]);
    acc[2] = fmaf(a, wA.z, acc[2]); acc[3] = fmaf(a, wA.w, acc[3]);
    acc[4] = fmaf(a, wB.x, acc[4]); acc[5] = fmaf(a, wB.y, acc[5]);
    acc[6] = fmaf(a, wB.z, acc[6]); acc[7] = fmaf(a, wB.w, acc[7]);
}

// ---------------- small helpers ----------------
__global__ void zero_kernel(float* p, int n) {
    int i = blockIdx.x * blockDim.x + threadIdx.x;
    if (i < n) p[i] = 0.f;
}

__global__ void deg_kernel(const int* __restrict__ dst) {
    int i = blockIdx.x * blockDim.x + threadIdx.x;
    if (i < N_EDGES) atomicAdd(&g_deg[dst[i]], 1.f);
}

__global__ void node_enc_kernel(const float* __restrict__ x,
                                const float* __restrict__ w,
                                const float* __restrict__ b) {
    __shared__ float xs[DIN_N];
    int nidx = blockIdx.x;
    int j = threadIdx.x;
    if (j < DIN_N) xs[j] = x[(size_t)nidx * DIN_N + j];
    __syncthreads();
    float acc = b[j];
#pragma unroll 8
    for (int k = 0; k < DIN_N; k++) acc = fmaf(xs[k], w[k * DN + j], acc);
    g_h[(size_t)nidx * DN + j] = acc;
}

__global__ void edge_enc_kernel(const float* __restrict__ ea,
                                const float* __restrict__ w,
                                const float* __restrict__ b) {
    __shared__ float es[4][DIN_E];
    int base = blockIdx.x * 4;
    int tid = threadIdx.x;
    if (tid < 64) es[tid >> 4][tid & 15] = ea[(size_t)base * DIN_E + tid];
    __syncthreads();
    int i = tid >> 6;
    int j = tid & 63;
    float acc = b[j];
#pragma unroll
    for (int k = 0; k < DIN_E; k++) acc = fmaf(es[i][k], w[k * DE + j], acc);
    g_e[(size_t)(base + i) * DE + j] = acc;
}

// ---------------- per-layer precompute: g_pre[n] = [h@mw | h@W1a | h@W1b], also zeros g_m ----------------
__global__ void __launch_bounds__(256, 1)
pre_kernel(const float* __restrict__ mw, const float* __restrict__ w1) {
    extern __shared__ float sm[];
    float* w_s = sm;               // 3 * 128*64 = 24576 : [mw | w1a | w1b]
    float* h_s = w_s + 24576;      // 128 * 132

    const int tid = threadIdx.x;
    for (int idx = tid; idx < DN * DHID; idx += 256) {
        w_s[idx]         = mw[idx];
        w_s[8192 + idx]  = w1[idx];            // w1 rows 0..127  (hs block)
        w_s[16384 + idx] = w1[8192 + idx];     // w1 rows 128..255 (hd block)
    }
    __syncthreads();

    const int q = tid >> 3, r = tid & 7, j0 = r << 3;
    const int e0 = q << 2;

    for (int tile = blockIdx.x * TP; tile < N_NODES; tile += gridDim.x * TP) {
        for (int idx = tid; idx < TP * 32; idx += 256) {
            int row = idx >> 5, c = (idx & 31) << 2;
            int node = tile + row;
            float4 v = make_float4(0.f, 0.f, 0.f, 0.f);
            if (node < N_NODES) v = *(const float4*)(g_h + (size_t)node * DN + c);
            *(float4*)(h_s + row * 132 + c) = v;
        }
        for (int idx = tid; idx < TP * 16; idx += 256) {    // zero g_m for this layer
            int row = idx >> 4, c = (idx & 15) << 2;
            int node = tile + row;
            if (node < N_NODES)
                *(float4*)(g_m + (size_t)node * DE + c) = make_float4(0.f, 0.f, 0.f, 0.f);
        }
        __syncthreads();

#pragma unroll
        for (int blk = 0; blk < 3; blk++) {
            const float* wb = w_s + blk * 8192;
            float acc[4][8];
#pragma unroll
            for (int e = 0; e < 4; e++)
#pragma unroll
                for (int c = 0; c < 8; c++) acc[e][c] = 0.f;
#pragma unroll 2
            for (int k = 0; k < DN; k += 4) {
                float4 av[4];
#pragma unroll
                for (int e = 0; e < 4; e++)
                    av[e] = *(const float4*)(h_s + (e0 + e) * 132 + k);
#pragma unroll
                for (int kk = 0; kk < 4; kk++) {
                    float4 wA = *(const float4*)(wb + (k + kk) * 64 + j0);
                    float4 wB = *(const float4*)(wb + (k + kk) * 64 + j0 + 4);
#pragma unroll
                    for (int e = 0; e < 4; e++) fma8(acc[e], (&av[e].x)[kk], wA, wB);
                }
            }
#pragma unroll
            for (int e = 0; e < 4; e++) {
                int node = tile + e0 + e;
                if (node < N_NODES) {
                    float* op = g_pre + (size_t)node * 192 + blk * 64 + j0;
                    *(float4*)op       = make_float4(acc[e][0], acc[e][1], acc[e][2], acc[e][3]);
                    *(float4*)(op + 4) = make_float4(acc[e][4], acc[e][5], acc[e][6], acc[e][7]);
                }
            }
        }
        __syncthreads();
    }
}

// ---------------- per-layer edge update ----------------
// t = e + m0[src]; u = relu(p1[src]+p2[dst] + t@W1c + b1); e_new = e + u@w2 + b2; scatter m[dst]
__global__ void __launch_bounds__(256, 2)
edge_layer_kernel(const int* __restrict__ src, const int* __restrict__ dst,
                  const float* __restrict__ w1c, const float* __restrict__ b1,
                  const float* __restrict__ w2, const float* __restrict__ b2) {
    extern __shared__ float sm[];
    float* w1_s = sm;             // 4096
    float* w2_s = w1_s + 4096;    // 4096
    float* b1_s = w2_s + 4096;    // 64
    float* b2_s = b1_s + 64;      // 64
    float* t_s  = b2_s + 64;      // 128*68

    const int tid = threadIdx.x;
    for (int idx = tid; idx < 4096; idx += 256) { w1_s[idx] = w1c[idx]; w2_s[idx] = w2[idx]; }
    if (tid < 64) b1_s[tid] = b1[tid];
    else if (tid < 128) b2_s[tid - 64] = b2[tid - 64];
    __syncthreads();

    const int q = tid >> 3, r = tid & 7, j0 = r << 3;
    const int e0 = q << 2;

    for (int tile = blockIdx.x * TEE; tile < N_EDGES; tile += gridDim.x * TEE) {
        int eid[4], dn[4];
        bool okk[4];
        float pS[4][8];           // p1[src]+p2[dst] slice, in regs
#pragma unroll
        for (int e = 0; e < 4; e++) {
            int ei = tile + e0 + e;
            okk[e] = ei < N_EDGES;
            eid[e] = okk[e] ? ei : 0;
            int s = src[eid[e]];
            dn[e] = dst[eid[e]];
            const float4* p1 = (const float4*)(g_pre + (size_t)s * 192 + 64 + j0);
            const float4* p2 = (const float4*)(g_pre + (size_t)dn[e] * 192 + 128 + j0);
            float4 a0 = p1[0], a1 = p1[1], c0 = p2[0], c1 = p2[1];
            pS[e][0] = a0.x + c0.x; pS[e][1] = a0.y + c0.y;
            pS[e][2] = a0.z + c0.z; pS[e][3] = a0.w + c0.w;
            pS[e][4] = a1.x + c1.x; pS[e][5] = a1.y + c1.y;
            pS[e][6] = a1.z + c1.z; pS[e][7] = a1.w + c1.w;
        }
        // cooperative t = e + m0[src]
        for (int idx = tid; idx < TEE * 16; idx += 256) {
            int row = idx >> 4, c = (idx & 15) << 2;
            int ei = tile + row;
            int ee = ei < N_EDGES ? ei : 0;
            int s = src[ee];
            float4 ev = *(const float4*)(g_e + (size_t)ee * DE + c);
            float4 mv = *(const float4*)(g_pre + (size_t)s * 192 + c);
            *(float4*)(t_s + row * 68 + c) =
                make_float4(ev.x + mv.x, ev.y + mv.y, ev.z + mv.z, ev.w + mv.w);
        }
        __syncthreads();

        // gemm1: acc = t @ W1c
        float acc[4][8];
#pragma unroll
        for (int e = 0; e < 4; e++)
#pragma unroll
            for (int c = 0; c < 8; c++) acc[e][c] = 0.f;
#pragma unroll 2
        for (int k = 0; k < DE; k += 4) {
            float4 av[4];
#pragma unroll
            for (int e = 0; e < 4; e++)
                av[e] = *(const float4*)(t_s + (e0 + e) * 68 + k);
#pragma unroll
            for (int kk = 0; kk < 4; kk++) {
                float4 wA = *(const float4*)(w1_s + (k + kk) * 64 + j0);
                float4 wB = *(const float4*)(w1_s + (k + kk) * 64 + j0 + 4);
#pragma unroll
                for (int e = 0; e < 4; e++) fma8(acc[e], (&av[e].x)[kk], wA, wB);
            }
        }

        // prefetch e-slices for residual (consumed after gemm2)
        float4 eS[4][2];
#pragma unroll
        for (int e = 0; e < 4; e++) {
            const float4* ep = (const float4*)(g_e + (size_t)eid[e] * DE + j0);
            eS[e][0] = ep[0]; eS[e][1] = ep[1];
        }

        // u = relu(acc + pS + b1), overlay into t_s (rows owned by this warp's quad)
        __syncwarp();
#pragma unroll
        for (int e = 0; e < 4; e++)
#pragma unroll
            for (int c = 0; c < 8; c++)
                t_s[(e0 + e) * 68 + j0 + c] = fmaxf(acc[e][c] + pS[e][c] + b1_s[j0 + c], 0.f);
        __syncwarp();

        // gemm2: a2 = u @ w2
        float a2[4][8];
#pragma unroll
        for (int e = 0; e < 4; e++)
#pragma unroll
            for (int c = 0; c < 8; c++) a2[e][c] = 0.f;
#pragma unroll 2
        for (int k = 0; k < DHID; k += 4) {
            float4 av[4];
#pragma unroll
            for (int e = 0; e < 4; e++)
                av[e] = *(const float4*)(t_s + (e0 + e) * 68 + k);
#pragma unroll
            for (int kk = 0; kk < 4; kk++) {
                float4 wA = *(const float4*)(w2_s + (k + kk) * 64 + j0);
                float4 wB = *(const float4*)(w2_s + (k + kk) * 64 + j0 + 4);
#pragma unroll
                for (int e = 0; e < 4; e++) fma8(a2[e], (&av[e].x)[kk], wA, wB);
            }
        }

        // e_new = e + a2 + b2 ; store + scatter
#pragma unroll
        for (int e = 0; e < 4; e++) {
            if (!okk[e]) continue;
            float v[8];
            v[0] = a2[e][0] + eS[e][0].x + b2_s[j0 + 0];
            v[1] = a2[e][1] + eS[e][0].y + b2_s[j0 + 1];
            v[2] = a2[e][2] + eS[e][0].z + b2_s[j0 + 2];
            v[3] = a2[e][3] + eS[e][0].w + b2_s[j0 + 3];
            v[4] = a2[e][4] + eS[e][1].x + b2_s[j0 + 4];
            v[5] = a2[e][5] + eS[e][1].y + b2_s[j0 + 5];
            v[6] = a2[e][6] + eS[e][1].z + b2_s[j0 + 6];
            v[7] = a2[e][7] + eS[e][1].w + b2_s[j0 + 7];
            float* eo = g_e + (size_t)eid[e] * DE + j0;
            *(float4*)eo       = make_float4(v[0], v[1], v[2], v[3]);
            *(float4*)(eo + 4) = make_float4(v[4], v[5], v[6], v[7]);
            float* mo = g_m + (size_t)dn[e] * DE + j0;
#pragma unroll
            for (int c = 0; c < 8; c++) atomicAdd(mo + c, v[c]);
        }
        __syncthreads();
    }
}

// ---------------- per-layer node update ----------------
__global__ void __launch_bounds__(256, 1)
node_layer_kernel(const float* __restrict__ w1, const float* __restrict__ b1,
                  const float* __restrict__ w2, const float* __restrict__ b2) {
    extern __shared__ float sm[];
    float* w1_s = sm;                 // 192*64 = 12288
    float* w2_s = w1_s + 12288;       // 64*128 = 8192
    float* b1_s = w2_s + 8192;        // 64
    float* b2_s = b1_s + 64;          // 128
    float* hm_s = b2_s + 128;         // 128*196
    float* u_s  = hm_s + TNN * 196;   // 128*68

    const int tid = threadIdx.x;
    for (int idx = tid; idx < (DN + DE) * DHID; idx += 256) w1_s[idx] = w1[idx];
    for (int idx = tid; idx < DHID * DN; idx += 256) w2_s[idx] = w2[idx];
    if (tid < DHID) b1_s[tid] = b1[tid];
    if (tid < DN)   b2_s[tid] = b2[tid];
    __syncthreads();

    const int q = tid >> 3, r = tid & 7, j0 = r << 3, j0b = r << 4;
    const int e0 = q << 2;

    for (int tile = blockIdx.x * TNN; tile < N_NODES; tile += gridDim.x * TNN) {
        for (int idx = tid; idx < TNN * 32; idx += 256) {
            int row = idx >> 5, c = (idx & 31) << 2;
            int node = tile + row;
            float4 v = make_float4(0.f, 0.f, 0.f, 0.f);
            if (node < N_NODES) v = *(const float4*)(g_h + (size_t)node * DN + c);
            *(float4*)(hm_s + row * 196 + c) = v;
        }
        for (int idx = tid; idx < TNN * 16; idx += 256) {
            int row = idx >> 4, c = (idx & 15) << 2;
            int node = tile + row;
            float4 v = make_float4(0.f, 0.f, 0.f, 0.f);
            if (node < N_NODES) {
                float inv = 1.f / fmaxf(g_deg[node], 1.f);
                float4 mv = *(const float4*)(g_m + (size_t)node * DE + c);
                v = make_float4(mv.x * inv, mv.y * inv, mv.z * inv, mv.w * inv);
            }
            *(float4*)(hm_s + row * 196 + 128 + c) = v;
        }
        __syncthreads();

        // gemm1: u = relu([h,m] @ w1 + b1)
        float acc[4][8];
#pragma unroll
        for (int e = 0; e < 4; e++)
#pragma unroll
            for (int c = 0; c < 8; c++) acc[e][c] = 0.f;
#pragma unroll 2
        for (int k = 0; k < DN + DE; k += 4) {
            float4 av[4];
#pragma unroll
            for (int e = 0; e < 4; e++)
                av[e] = *(const float4*)(hm_s + (e0 + e) * 196 + k);
#pragma unroll
            for (int kk = 0; kk < 4; kk++) {
                float4 wA = *(const float4*)(w1_s + (k + kk) * 64 + j0);
                float4 wB = *(const float4*)(w1_s + (k + kk) * 64 + j0 + 4);
#pragma unroll
                for (int e = 0; e < 4; e++) fma8(acc[e], (&av[e].x)[kk], wA, wB);
            }
        }
        __syncwarp();
#pragma unroll
        for (int e = 0; e < 4; e++)
#pragma unroll
            for (int c = 0; c < 8; c++)
                u_s[(e0 + e) * 68 + j0 + c] = fmaxf(acc[e][c] + b1_s[j0 + c], 0.f);
        __syncwarp();

        // gemm2: h += u @ w2 + b2    (16 out cols / thread)
        float a2[4][16];
#pragma unroll
        for (int e = 0; e < 4; e++)
#pragma unroll
            for (int c = 0; c < 16; c++) a2[e][c] = 0.f;
#pragma unroll 2
        for (int k = 0; k < DHID; k += 4) {
            float4 av[4];
#pragma unroll
            for (int e = 0; e < 4; e++)
                av[e] = *(const float4*)(u_s + (e0 + e) * 68 + k);
#pragma unroll
            for (int kk = 0; kk < 4; kk++) {
                float4 w0 = *(const float4*)(w2_s + (k + kk) * 128 + j0b);
                float4 w1v = *(const float4*)(w2_s + (k + kk) * 128 + j0b + 4);
                float4 w2v = *(const float4*)(w2_s + (k + kk) * 128 + j0b + 8);
                float4 w3v = *(const float4*)(w2_s + (k + kk) * 128 + j0b + 12);
#pragma unroll
                for (int e = 0; e < 4; e++) {
                    float a = (&av[e].x)[kk];
                    fma8(a2[e], a, w0, w1v);
                    fma8(a2[e] + 8, a, w2v, w3v);
                }
            }
        }
#pragma unroll
        for (int e = 0; e < 4; e++) {
            int node = tile + e0 + e;
            if (node < N_NODES) {
                float* ho = g_h + (size_t)node * DN + j0b;
#pragma unroll
                for (int cq = 0; cq < 4; cq++) {
                    float4 o;
                    o.x = hm_s[(e0 + e) * 196 + j0b + 4 * cq]     + a2[e][4 * cq]     + b2_s[j0b + 4 * cq];
                    o.y = hm_s[(e0 + e) * 196 + j0b + 4 * cq + 1] + a2[e][4 * cq + 1] + b2_s[j0b + 4 * cq + 1];
                    o.z = hm_s[(e0 + e) * 196 + j0b + 4 * cq + 2] + a2[e][4 * cq + 2] + b2_s[j0b + 4 * cq + 2];
                    o.w = hm_s[(e0 + e) * 196 + j0b + 4 * cq + 3] + a2[e][4 * cq + 3] + b2_s[j0b + 4 * cq + 3];
                    *(float4*)(ho + 4 * cq) = o;
                }
            }
        }
        __syncthreads();
    }
}

// ---------------- readout (segmented: batch is sorted) ----------------
__global__ void readout_kernel(const int* __restrict__ batch) {
    int c = threadIdx.x;
    int n0 = blockIdx.x * 128;
    if (n0 >= N_NODES) return;
    int n1 = n0 + 128; if (n1 > N_NODES) n1 = N_NODES;
    int cur = batch[n0];
    float s = 0.f, cnt = 0.f;
    for (int node = n0; node < n1; node++) {
        int bb = batch[node];
        if (bb != cur) {
            atomicAdd(&g_gsum[cur * DN + c], s);
            if (c == 0) atomicAdd(&g_gcnt[cur], cnt);
            s = 0.f; cnt = 0.f; cur = bb;
        }
        s += g_h[(size_t)node * DN + c];
        cnt += 1.f;
    }
    atomicAdd(&g_gsum[cur * DN + c], s);
    if (c == 0) atomicAdd(&g_gcnt[cur], cnt);
}

__global__ void ro1_kernel(const float* __restrict__ w, const float* __restrict__ b) {
    __shared__ float gx[DN];
    int g = blockIdx.x, j = threadIdx.x;
    gx[j] = g_gsum[g * DN + j] / fmaxf(g_gcnt[g], 1.f);
    __syncthreads();
    float acc = b[j];
#pragma unroll 8
    for (int k = 0; k < DN; k++) acc = fmaf(gx[k], w[k * DN + j], acc);
    g_rtmp[g * DN + j] = fmaxf(acc, 0.f);
}

__global__ void ro2_kernel(const float* __restrict__ w, const float* __restrict__ b,
                           float* __restrict__ out) {
    __shared__ float gx[DN];
    int g = blockIdx.x, j = threadIdx.x;
    gx[j] = g_rtmp[g * DN + j];
    __syncthreads();
    float acc = b[j];
#pragma unroll 8
    for (int k = 0; k < DN; k++) acc = fmaf(gx[k], w[k * DN + j], acc);
    out[g * DN + j] = acc;
}

// ---------------- host ----------------
static const int PRE_SMEM_BYTES  = (24576 + TP * 132) * 4;                         // 165888
static const int EDGE_SMEM_BYTES = (4096 + 4096 + 64 + 64 + TEE * 68) * 4;         // 68096
static const int NODE_SMEM_BYTES = (12288 + 8192 + 64 + 128 + TNN * 196 + TNN * 68) * 4; // 217856

extern "C" void kernel_launch(void* const* d_in, const int* in_sizes, int n_in,
                              void* d_out, int out_size) {
    const float* x       = (const float*)d_in[0];
    const float* ea      = (const float*)d_in[1];
    const int*   eindex  = (const int*)d_in[2];
    const int*   batch   = (const int*)d_in[3];
    const float* lin_x_w = (const float*)d_in[4];
    const float* lin_x_b = (const float*)d_in[5];
    const float* lin_e_w = (const float*)d_in[6];
    const float* lin_e_b = (const float*)d_in[7];
    const float* msg_w   = (const float*)d_in[8];
    const float* pe_w1   = (const float*)d_in[9];
    const float* pe_b1   = (const float*)d_in[10];
    const float* pe_w2   = (const float*)d_in[11];
    const float* pe_b2   = (const float*)d_in[12];
    const float* pv_w1   = (const float*)d_in[13];
    const float* pv_b1   = (const float*)d_in[14];
    const float* pv_w2   = (const float*)d_in[15];
    const float* pv_b2   = (const float*)d_in[16];
    const float* ro_w1   = (const float*)d_in[17];
    const float* ro_b1   = (const float*)d_in[18];
    const float* ro_w2   = (const float*)d_in[19];
    const float* ro_b2   = (const float*)d_in[20];
    const int* src = eindex;
    const int* dst = eindex + N_EDGES;

    cudaFuncSetAttribute(pre_kernel,  cudaFuncAttributeMaxDynamicSharedMemorySize, PRE_SMEM_BYTES);
    cudaFuncSetAttribute(edge_layer_kernel, cudaFuncAttributeMaxDynamicSharedMemorySize, EDGE_SMEM_BYTES);
    cudaFuncSetAttribute(node_layer_kernel, cudaFuncAttributeMaxDynamicSharedMemorySize, NODE_SMEM_BYTES);

    float *p_deg, *p_gs, *p_gc;
    cudaGetSymbolAddress((void**)&p_deg, g_deg);
    cudaGetSymbolAddress((void**)&p_gs,  g_gsum);
    cudaGetSymbolAddress((void**)&p_gc,  g_gcnt);

    // index 3 = edge_layer(l=0)  (profiler captures launch #3)
    node_enc_kernel<<<N_NODES, 128>>>(x, lin_x_w, lin_x_b);                 // 0
    edge_enc_kernel<<<N_EDGES / 4, 256>>>(ea, lin_e_w, lin_e_b);            // 1
    pre_kernel<<<148, 256, PRE_SMEM_BYTES>>>(msg_w, pe_w1);                 // 2 (also zeros g_m)
    edge_layer_kernel<<<296, 256, EDGE_SMEM_BYTES>>>(                       // 3
        src, dst, pe_w1 + 2 * DN * DHID, pe_b1, pe_w2, pe_b2);
    zero_kernel<<<(N_NODES + 255) / 256, 256>>>(p_deg, N_NODES);            // 4
    deg_kernel<<<(N_EDGES + 255) / 256, 256>>>(dst);                        // 5
    node_layer_kernel<<<148, 256, NODE_SMEM_BYTES>>>(                       // 6
        pv_w1, pv_b1, pv_w2, pv_b2);

    for (int l = 1; l < NL; l++) {
        pre_kernel<<<148, 256, PRE_SMEM_BYTES>>>(
            msg_w + (size_t)l * DN * DE,
            pe_w1 + (size_t)l * (DE + 2 * DN) * DHID);
        edge_layer_kernel<<<296, 256, EDGE_SMEM_BYTES>>>(
            src, dst,
            pe_w1 + (size_t)l * (DE + 2 * DN) * DHID + 2 * DN * DHID,
            pe_b1 + (size_t)l * DHID,
            pe_w2 + (size_t)l * DHID * DE,
            pe_b2 + (size_t)l * DE);
        node_layer_kernel<<<148, 256, NODE_SMEM_BYTES>>>(
            pv_w1 + (size_t)l * (DN + DE) * DHID,
            pv_b1 + (size_t)l * DHID,
            pv_w2 + (size_t)l * DHID * DN,
            pv_b2 + (size_t)l * DN);
    }

    zero_kernel<<<(NB * DN + 255) / 256, 256>>>(p_gs, NB * DN);
    zero_kernel<<<1, 64>>>(p_gc, NB);
    readout_kernel<<<(N_NODES + 127) / 128, 128>>>(batch);
    ro1_kernel<<<NB, DN>>>(ro_w1, ro_b1);
    ro2_kernel<<<NB, DN>>>(ro_w2, ro_b2, (float*)d_out);
}